// round 1
// baseline (speedup 1.0000x reference)
#include <cuda_runtime.h>
#include <cuda_bf16.h>
#include <cstdint>

// ---------------------------------------------------------------------------
// CrossAttentionBlock fused implementation (round 0: legacy bf16 mma.sync)
//
//   q   = LN(img) @ wq                    [B, N, C]
//   ctx = concat(param@w_param+b, obj@w_obj+b)   [B, 2, C]
//   k,v = split(LN(ctx) @ w_kv)           [B, 2, C] each
//   per head: softmax over 2 scores, o = w0*v0 + w1*v1
//   out = o @ w_out + b_out + img
// ---------------------------------------------------------------------------

#define B_    16
#define NIMG  4096
#define C_    768
#define H_    12
#define D_    64
#define P_    128
#define O_    64
#define TM    128      // rows per CTA in the big GEMMs
#define BK    64       // K-tile
#define NC_   128      // N-chunk (2 heads)
#define XS    776      // A-tile smem row stride in halves (16B aligned, conflict-free)
#define BTS   136      // B-tile smem row stride in halves (conflict-free)

#define SMEM_XN (TM * XS * 2)            // 198656 B
#define SMEM_BT (BK * BTS * 2)           // 17408 B
#define SMEM_KV (2 * 2 * C_ * 4)         // 12288 B (k[2][768], v[2][768] fp32)
#define SMEM_Q  (SMEM_XN + SMEM_BT + SMEM_KV)  // 228352
#define SMEM_O  (SMEM_XN + SMEM_BT)            // 216064

// ---- device scratch (allocation-free rule: __device__ globals) ----
static __device__ __nv_bfloat16 g_wq_bf[C_ * C_];
static __device__ __nv_bfloat16 g_wo_bf[C_ * C_];
static __device__ float g_ln[B_ * 2 * C_];
static __device__ float g_k[B_ * 2 * C_];
static __device__ float g_v[B_ * 2 * C_];
static __device__ __nv_bfloat16 g_os[(size_t)B_ * NIMG * C_];   // o scratch (bf16)

// ---------------------------------------------------------------------------
// small helpers
// ---------------------------------------------------------------------------
__device__ __forceinline__ void ldsm4(uint32_t* r, uint32_t a) {
    asm volatile("ldmatrix.sync.aligned.m8n8.x4.shared.b16 {%0,%1,%2,%3}, [%4];"
                 : "=r"(r[0]), "=r"(r[1]), "=r"(r[2]), "=r"(r[3]) : "r"(a));
}
__device__ __forceinline__ void ldsm4t(uint32_t* r, uint32_t a) {
    asm volatile("ldmatrix.sync.aligned.m8n8.x4.trans.shared.b16 {%0,%1,%2,%3}, [%4];"
                 : "=r"(r[0]), "=r"(r[1]), "=r"(r[2]), "=r"(r[3]) : "r"(a));
}
__device__ __forceinline__ void mma16816(float* d, const uint32_t* a, const uint32_t* b) {
    asm volatile(
        "mma.sync.aligned.m16n8k16.row.col.f32.bf16.bf16.f32 "
        "{%0,%1,%2,%3},{%4,%5,%6,%7},{%8,%9},{%0,%1,%2,%3};"
        : "+f"(d[0]), "+f"(d[1]), "+f"(d[2]), "+f"(d[3])
        : "r"(a[0]), "r"(a[1]), "r"(a[2]), "r"(a[3]), "r"(b[0]), "r"(b[1]));
}

// ---------------------------------------------------------------------------
// kernel: convert fp32 weight matrix -> bf16 device global
// grid = C_*C_/4/256 = 576, block = 256
// ---------------------------------------------------------------------------
__global__ void cab_cvt_kernel(const float* __restrict__ src, int which) {
    __nv_bfloat16* dst = which ? g_wo_bf : g_wq_bf;
    int i = blockIdx.x * 256 + threadIdx.x;         // i < 147456
    float4 v = reinterpret_cast<const float4*>(src)[i];
    __nv_bfloat162* d2 = reinterpret_cast<__nv_bfloat162*>(dst);
    d2[2 * i]     = __floats2bfloat162_rn(v.x, v.y);
    d2[2 * i + 1] = __floats2bfloat162_rn(v.z, v.w);
}

// ---------------------------------------------------------------------------
// kernel: context projections + layernorm -> g_ln[b][2][C]
// grid = B_, block = 256
// ---------------------------------------------------------------------------
__global__ void cab_ctx_a_kernel(const float* __restrict__ ptk, const float* __restrict__ obj,
                                 const float* __restrict__ wpar, const float* __restrict__ bpar,
                                 const float* __restrict__ wobj, const float* __restrict__ bobj,
                                 const float* __restrict__ cnw, const float* __restrict__ cnb) {
    __shared__ float sprm[P_], sobj[O_];
    __shared__ float rbuf[8][4];
    __shared__ float stats[4];
    const int tid = threadIdx.x, lane = tid & 31, wid = tid >> 5;
    const int b = blockIdx.x;

    for (int i = tid; i < P_; i += 256) sprm[i] = ptk[b * P_ + i];
    if (tid < O_) sobj[tid] = obj[b * O_ + tid];
    __syncthreads();

    float pv[3], ov[3];
    float s_p = 0.f, q_p = 0.f, s_o = 0.f, q_o = 0.f;
    #pragma unroll
    for (int u = 0; u < 3; ++u) {
        const int c = tid + 256 * u;
        float ap = bpar[c];
        #pragma unroll 8
        for (int j = 0; j < P_; ++j) ap += sprm[j] * wpar[j * C_ + c];
        float ao = bobj[c];
        #pragma unroll 8
        for (int j = 0; j < O_; ++j) ao += sobj[j] * wobj[j * C_ + c];
        pv[u] = ap; ov[u] = ao;
        s_p += ap; q_p += ap * ap; s_o += ao; q_o += ao * ao;
    }
    #pragma unroll
    for (int o = 16; o; o >>= 1) {
        s_p += __shfl_xor_sync(~0u, s_p, o);
        q_p += __shfl_xor_sync(~0u, q_p, o);
        s_o += __shfl_xor_sync(~0u, s_o, o);
        q_o += __shfl_xor_sync(~0u, q_o, o);
    }
    if (lane == 0) { rbuf[wid][0] = s_p; rbuf[wid][1] = q_p; rbuf[wid][2] = s_o; rbuf[wid][3] = q_o; }
    __syncthreads();
    if (tid == 0) {
        float a = 0.f, bq = 0.f, cc = 0.f, d = 0.f;
        for (int w = 0; w < 8; ++w) { a += rbuf[w][0]; bq += rbuf[w][1]; cc += rbuf[w][2]; d += rbuf[w][3]; }
        const float mp = a / C_,  vp = bq / C_ - mp * mp;
        const float mo = cc / C_, vo = d / C_ - mo * mo;
        stats[0] = mp; stats[1] = rsqrtf(vp + 1e-5f);
        stats[2] = mo; stats[3] = rsqrtf(vo + 1e-5f);
    }
    __syncthreads();
    const float mp = stats[0], rp = stats[1], mo = stats[2], ro = stats[3];
    #pragma unroll
    for (int u = 0; u < 3; ++u) {
        const int c = tid + 256 * u;
        g_ln[(b * 2 + 0) * C_ + c] = (pv[u] - mp) * rp * cnw[c] + cnb[c];
        g_ln[(b * 2 + 1) * C_ + c] = (ov[u] - mo) * ro * cnw[c] + cnb[c];
    }
}

// ---------------------------------------------------------------------------
// kernel: kv = LN(ctx) @ w_kv -> g_k, g_v.  grid = (B_, 16), block = 192
// each CTA computes a 96-column slice of the 1536-wide kv for both ctx rows
// ---------------------------------------------------------------------------
__global__ void cab_ctx_b_kernel(const float* __restrict__ wkv) {
    __shared__ float ln0[C_], ln1[C_];
    const int tid = threadIdx.x;
    const int b = blockIdx.x, sl = blockIdx.y;
    for (int i = tid; i < C_; i += 192) {
        ln0[i] = g_ln[(b * 2 + 0) * C_ + i];
        ln1[i] = g_ln[(b * 2 + 1) * C_ + i];
    }
    __syncthreads();
    const int row = tid / 96, ccl = tid % 96;
    const int cg = sl * 96 + ccl;                 // 0..1535
    const float* lnr = row ? ln1 : ln0;
    float a0 = 0.f, a1 = 0.f, a2 = 0.f, a3 = 0.f;
    for (int c = 0; c < C_; c += 4) {
        a0 += lnr[c + 0] * wkv[(size_t)(c + 0) * (2 * C_) + cg];
        a1 += lnr[c + 1] * wkv[(size_t)(c + 1) * (2 * C_) + cg];
        a2 += lnr[c + 2] * wkv[(size_t)(c + 2) * (2 * C_) + cg];
        a3 += lnr[c + 3] * wkv[(size_t)(c + 3) * (2 * C_) + cg];
    }
    const float r = (a0 + a1) + (a2 + a3);
    if (cg < C_) g_k[(b * 2 + row) * C_ + cg]        = r;
    else         g_v[(b * 2 + row) * C_ + (cg - C_)] = r;
}

// ---------------------------------------------------------------------------
// shared GEMM inner block: one 128x128 N-chunk, K=768, A in smem (bf16),
// weights streamed from bf16 global through a single-buffered smem tile with
// register prefetch.  8 warps as 4(M) x 2(N); warp tile 32x64.
// ---------------------------------------------------------------------------
__device__ __forceinline__ void cab_gemm_chunk(
    const __nv_bfloat16* __restrict__ wsrc, __nv_bfloat16* bt,
    uint32_t xnb, uint32_t btb, int ncx, int tid, int lane, int wm, int wn,
    float acc[2][8][4])
{
    #pragma unroll
    for (int mi = 0; mi < 2; ++mi)
        #pragma unroll
        for (int ni = 0; ni < 8; ++ni)
            #pragma unroll
            for (int r = 0; r < 4; ++r) acc[mi][ni][r] = 0.f;

    uint4 pf[4];
    #pragma unroll
    for (int j = 0; j < 4; ++j) {
        const int c = j * 256 + tid;
        pf[j] = *reinterpret_cast<const uint4*>(
            wsrc + (size_t)(c >> 4) * C_ + ncx * NC_ + (c & 15) * 8);
    }
    for (int kt = 0; kt < 12; ++kt) {
        __syncthreads();
        #pragma unroll
        for (int j = 0; j < 4; ++j) {
            const int c = j * 256 + tid;
            *reinterpret_cast<uint4*>(bt + (c >> 4) * BTS + (c & 15) * 8) = pf[j];
        }
        if (kt < 11) {
            #pragma unroll
            for (int j = 0; j < 4; ++j) {
                const int c = j * 256 + tid;
                pf[j] = *reinterpret_cast<const uint4*>(
                    wsrc + (size_t)((kt + 1) * BK + (c >> 4)) * C_ + ncx * NC_ + (c & 15) * 8);
            }
        }
        __syncthreads();
        #pragma unroll
        for (int ks = 0; ks < 4; ++ks) {
            const int kb = kt * BK + ks * 16;
            uint32_t a0[4], a1[4];
            ldsm4(a0, xnb + (((wm * 32 +      (lane & 15)) * XS + kb + (lane >> 4) * 8) << 1));
            ldsm4(a1, xnb + (((wm * 32 + 16 + (lane & 15)) * XS + kb + (lane >> 4) * 8) << 1));
            #pragma unroll
            for (int nt = 0; nt < 4; ++nt) {
                uint32_t bb4[4];
                ldsm4t(bb4, btb + (((ks * 16 + (lane & 15)) * BTS +
                                    wn * 64 + nt * 16 + (lane >> 4) * 8) << 1));
                mma16816(acc[0][2 * nt],     a0, bb4);
                mma16816(acc[0][2 * nt + 1], a0, bb4 + 2);
                mma16816(acc[1][2 * nt],     a1, bb4);
                mma16816(acc[1][2 * nt + 1], a1, bb4 + 2);
            }
        }
    }
}

// ---------------------------------------------------------------------------
// kernel: LN(img) -> q GEMM -> per-head softmax-over-2 -> o (bf16 scratch)
// grid = (NIMG/TM, B_), block = 256, dyn smem = SMEM_Q
// ---------------------------------------------------------------------------
__global__ void __launch_bounds__(256)
cab_qattn_kernel(const float* __restrict__ x,
                 const float* __restrict__ lw, const float* __restrict__ lb) {
    extern __shared__ unsigned char sm[];
    __nv_bfloat16* xn = reinterpret_cast<__nv_bfloat16*>(sm);
    __nv_bfloat16* bt = reinterpret_cast<__nv_bfloat16*>(sm + SMEM_XN);
    float* kk = reinterpret_cast<float*>(sm + SMEM_XN + SMEM_BT);
    float* vv = kk + 2 * C_;

    const int tid = threadIdx.x, lane = tid & 31, wid = tid >> 5;
    const int b = blockIdx.y, row0 = blockIdx.x * TM;

    for (int i = tid; i < 2 * C_; i += 256) {
        kk[i] = g_k[b * 2 * C_ + i];
        vv[i] = g_v[b * 2 * C_ + i];
    }

    // ---- stage 0: per-row layernorm, write bf16 A tile ----
    float2 wv[12], bv[12];
    #pragma unroll
    for (int i = 0; i < 12; ++i) {
        wv[i] = *reinterpret_cast<const float2*>(lw + 2 * lane + 64 * i);
        bv[i] = *reinterpret_cast<const float2*>(lb + 2 * lane + 64 * i);
    }
    for (int r = 0; r < 16; ++r) {
        const int row = wid * 16 + r;
        const float2* xr = reinterpret_cast<const float2*>(
            x + ((size_t)b * NIMG + row0 + row) * C_);
        float2 xv[12];
        float s = 0.f, s2 = 0.f;
        #pragma unroll
        for (int i = 0; i < 12; ++i) {
            const float2 t = xr[lane + 32 * i];
            xv[i] = t;
            s  += t.x + t.y;
            s2 += t.x * t.x + t.y * t.y;
        }
        #pragma unroll
        for (int o = 16; o; o >>= 1) {
            s  += __shfl_xor_sync(~0u, s,  o);
            s2 += __shfl_xor_sync(~0u, s2, o);
        }
        const float mean = s * (1.f / C_);
        const float var  = s2 * (1.f / C_) - mean * mean;
        const float rstd = rsqrtf(var + 1e-5f);
        __nv_bfloat16* xrow = xn + row * XS;
        #pragma unroll
        for (int i = 0; i < 12; ++i) {
            const float a0 = (xv[i].x - mean) * rstd * wv[i].x + bv[i].x;
            const float a1 = (xv[i].y - mean) * rstd * wv[i].y + bv[i].y;
            *reinterpret_cast<__nv_bfloat162*>(xrow + 2 * lane + 64 * i) =
                __floats2bfloat162_rn(a0, a1);
        }
    }
    __syncthreads();

    const uint32_t xnb = (uint32_t)__cvta_generic_to_shared(xn);
    const uint32_t btb = (uint32_t)__cvta_generic_to_shared(bt);
    const int wm = wid & 3, wn = wid >> 2;

    for (int ncx = 0; ncx < 6; ++ncx) {
        float acc[2][8][4];
        cab_gemm_chunk(g_wq_bf, bt, xnb, btb, ncx, tid, lane, wm, wn, acc);

        // ---- attention epilogue: warp owns exactly one head (64 cols) ----
        const int head = ncx * 2 + wn;
        const float* k0p = kk + head * D_;
        const float* k1p = kk + C_ + head * D_;
        const float* v0p = vv + head * D_;
        const float* v1p = vv + C_ + head * D_;
        #pragma unroll
        for (int mi = 0; mi < 2; ++mi) {
            #pragma unroll
            for (int rh = 0; rh < 2; ++rh) {
                float p0 = 0.f, p1 = 0.f;
                #pragma unroll
                for (int ni = 0; ni < 8; ++ni) {
                    #pragma unroll
                    for (int rl = 0; rl < 2; ++rl) {
                        const int cl = ni * 8 + (lane & 3) * 2 + rl;
                        const float qv = acc[mi][ni][rh * 2 + rl];
                        p0 += qv * k0p[cl];
                        p1 += qv * k1p[cl];
                    }
                }
                p0 += __shfl_xor_sync(~0u, p0, 1); p0 += __shfl_xor_sync(~0u, p0, 2);
                p1 += __shfl_xor_sync(~0u, p1, 1); p1 += __shfl_xor_sync(~0u, p1, 2);
                const float s0 = p0 * 0.125f, s1 = p1 * 0.125f;   // 1/sqrt(64)
                const float mx = fmaxf(s0, s1);
                const float e0 = __expf(s0 - mx), e1 = __expf(s1 - mx);
                const float w0 = e0 / (e0 + e1);
                const float w1 = 1.f - w0;
                const int rg = row0 + wm * 32 + mi * 16 + (lane >> 2) + rh * 8;
                __nv_bfloat16* od = g_os + ((size_t)b * NIMG + rg) * C_ + head * D_;
                #pragma unroll
                for (int ni = 0; ni < 8; ++ni) {
                    const int cle = ni * 8 + (lane & 3) * 2;
                    const float o0 = w0 * v0p[cle]     + w1 * v1p[cle];
                    const float o1 = w0 * v0p[cle + 1] + w1 * v1p[cle + 1];
                    *reinterpret_cast<__nv_bfloat162*>(od + cle) =
                        __floats2bfloat162_rn(o0, o1);
                }
            }
        }
    }
}

// ---------------------------------------------------------------------------
// kernel: out = o @ w_out + b_out + img
// grid = (NIMG/TM, B_), block = 256, dyn smem = SMEM_O
// ---------------------------------------------------------------------------
__global__ void __launch_bounds__(256)
cab_out_kernel(const float* __restrict__ x, const float* __restrict__ bout,
               float* __restrict__ out) {
    extern __shared__ unsigned char sm[];
    __nv_bfloat16* xn = reinterpret_cast<__nv_bfloat16*>(sm);
    __nv_bfloat16* bt = reinterpret_cast<__nv_bfloat16*>(sm + SMEM_XN);

    const int tid = threadIdx.x, lane = tid & 31, wid = tid >> 5;
    const int b = blockIdx.y, row0 = blockIdx.x * TM;

    // copy o tile (already bf16) into padded smem
    #pragma unroll
    for (int j = 0; j < 48; ++j) {
        const int c = j * 256 + tid;                 // c < 12288
        const int row = c / 96, ci = c % 96;
        *reinterpret_cast<uint4*>(xn + row * XS + ci * 8) =
            *reinterpret_cast<const uint4*>(
                g_os + ((size_t)b * NIMG + row0 + row) * C_ + ci * 8);
    }
    __syncthreads();

    const uint32_t xnb = (uint32_t)__cvta_generic_to_shared(xn);
    const uint32_t btb = (uint32_t)__cvta_generic_to_shared(bt);
    const int wm = wid & 3, wn = wid >> 2;

    for (int ncx = 0; ncx < 6; ++ncx) {
        float acc[2][8][4];
        cab_gemm_chunk(g_wo_bf, bt, xnb, btb, ncx, tid, lane, wm, wn, acc);

        // ---- epilogue: + bias + residual, fp32 store ----
        #pragma unroll
        for (int mi = 0; mi < 2; ++mi) {
            #pragma unroll
            for (int rh = 0; rh < 2; ++rh) {
                const int rg = row0 + wm * 32 + mi * 16 + (lane >> 2) + rh * 8;
                const float* xr = x + ((size_t)b * NIMG + rg) * C_;
                float* orow = out + ((size_t)b * NIMG + rg) * C_;
                #pragma unroll
                for (int ni = 0; ni < 8; ++ni) {
                    const int col = ncx * NC_ + wn * 64 + ni * 8 + (lane & 3) * 2;
                    const float2 xv = *reinterpret_cast<const float2*>(xr + col);
                    const float2 bo = *reinterpret_cast<const float2*>(bout + col);
                    float2 rr;
                    rr.x = acc[mi][ni][rh * 2 + 0] + bo.x + xv.x;
                    rr.y = acc[mi][ni][rh * 2 + 1] + bo.y + xv.y;
                    *reinterpret_cast<float2*>(orow + col) = rr;
                }
            }
        }
    }
}

// ---------------------------------------------------------------------------
// launch
// ---------------------------------------------------------------------------
extern "C" void kernel_launch(void* const* d_in, const int* in_sizes, int n_in,
                              void* d_out, int out_size) {
    const float* x    = (const float*)d_in[0];   // img_tokens   [B, N, C]
    const float* ptk  = (const float*)d_in[1];   // param_tokens [B, P]
    const float* obj  = (const float*)d_in[2];   // obj_emb      [B, O]
    const float* inw  = (const float*)d_in[3];   // img_norm_w   [C]
    const float* inb  = (const float*)d_in[4];   // img_norm_b   [C]
    const float* cnw  = (const float*)d_in[5];   // ctx_norm_w   [C]
    const float* cnb  = (const float*)d_in[6];   // ctx_norm_b   [C]
    const float* wq   = (const float*)d_in[7];   // [C, C]
    const float* wpar = (const float*)d_in[8];   // [P, C]
    const float* bpar = (const float*)d_in[9];   // [C]
    const float* wobj = (const float*)d_in[10];  // [O, C]
    const float* bobj = (const float*)d_in[11];  // [C]
    const float* wkv  = (const float*)d_in[12];  // [C, 2C]
    const float* wout = (const float*)d_in[13];  // [C, C]
    const float* bout = (const float*)d_in[14];  // [C]
    float* out = (float*)d_out;

    cudaFuncSetAttribute(cab_qattn_kernel,
                         cudaFuncAttributeMaxDynamicSharedMemorySize, SMEM_Q);
    cudaFuncSetAttribute(cab_out_kernel,
                         cudaFuncAttributeMaxDynamicSharedMemorySize, SMEM_O);

    cab_cvt_kernel<<<576, 256>>>(wq, 0);
    cab_cvt_kernel<<<576, 256>>>(wout, 1);
    cab_ctx_a_kernel<<<B_, 256>>>(ptk, obj, wpar, bpar, wobj, bobj, cnw, cnb);
    cab_ctx_b_kernel<<<dim3(B_, 16), 192>>>(wkv);
    cab_qattn_kernel<<<dim3(NIMG / TM, B_), 256, SMEM_Q>>>(x, inw, inb);
    cab_out_kernel<<<dim3(NIMG / TM, B_), 256, SMEM_O>>>(x, bout, out);
}

// round 2
// speedup vs baseline: 1.3075x; 1.3075x over previous
#include <cuda_runtime.h>
#include <cuda_bf16.h>
#include <cstdint>

// ---------------------------------------------------------------------------
// CrossAttentionBlock (round 1)
//   q   = LN(img) @ wq
//   ctx -> k,v (tiny)
//   attention weights w0,w1 per (row, head)   (softmax over 2)
//   vp[c,h,:] = v_c[h*64:(h+1)*64] @ w_out[h*64:(h+1)*64, :]   (fp32 exact)
//   out = watt @ vp + b_out + img         (K=24 combine, replaces big GEMM2)
// ---------------------------------------------------------------------------

#define B_    16
#define NIMG  4096
#define C_    768
#define H_    12
#define D_    64
#define P_    128
#define O_    64
#define TM    128
#define BK    32          // K-tile for cp.async pipeline
#define XS    776         // A-tile smem row stride (halves)
#define BTS   136         // B-tile smem row stride (halves)
#define WTS   40          // watt smem row stride (halves): 80B, conflict-free, 16B-aligned

#define SMEM_XN   (TM * XS * 2)               // 198656
#define SMEM_BTB  (BK * BTS * 2)              // 8704 per buffer
#define SMEM_KK   (2 * C_ * 4)                // 6144
#define SMEM_WATT (TM * WTS * 2)              // 10240
#define SMEM_MAIN (SMEM_XN + 2 * SMEM_BTB + SMEM_KK + SMEM_WATT)  // 232448

// ---- device scratch ----
static __device__ __nv_bfloat16 g_wq_bf[C_ * C_];
static __device__ float g_ln[B_ * 2 * C_];
static __device__ float g_k[B_ * 2 * C_];
static __device__ float g_v[B_ * 2 * C_];
static __device__ __nv_bfloat16 g_vp[B_ * 32 * C_];   // rows 24..31 stay zero

// ---------------------------------------------------------------------------
// helpers
// ---------------------------------------------------------------------------
__device__ __forceinline__ void ldsm4(uint32_t* r, uint32_t a) {
    asm volatile("ldmatrix.sync.aligned.m8n8.x4.shared.b16 {%0,%1,%2,%3}, [%4];"
                 : "=r"(r[0]), "=r"(r[1]), "=r"(r[2]), "=r"(r[3]) : "r"(a));
}
__device__ __forceinline__ void ldsm4t(uint32_t* r, uint32_t a) {
    asm volatile("ldmatrix.sync.aligned.m8n8.x4.trans.shared.b16 {%0,%1,%2,%3}, [%4];"
                 : "=r"(r[0]), "=r"(r[1]), "=r"(r[2]), "=r"(r[3]) : "r"(a));
}
__device__ __forceinline__ void mma16816(float* d, const uint32_t* a, const uint32_t* b) {
    asm volatile(
        "mma.sync.aligned.m16n8k16.row.col.f32.bf16.bf16.f32 "
        "{%0,%1,%2,%3},{%4,%5,%6,%7},{%8,%9},{%0,%1,%2,%3};"
        : "+f"(d[0]), "+f"(d[1]), "+f"(d[2]), "+f"(d[3])
        : "r"(a[0]), "r"(a[1]), "r"(a[2]), "r"(a[3]), "r"(b[0]), "r"(b[1]));
}
__device__ __forceinline__ void cp16(uint32_t dst, const void* src) {
    asm volatile("cp.async.cg.shared.global [%0], [%1], 16;" :: "r"(dst), "l"(src));
}
__device__ __forceinline__ void cp_commit() { asm volatile("cp.async.commit_group;"); }
__device__ __forceinline__ void cp_wait0()  { asm volatile("cp.async.wait_group 0;" ::: "memory"); }

// ---------------------------------------------------------------------------
// wq fp32 -> bf16
// ---------------------------------------------------------------------------
__global__ void cab_cvt_kernel(const float* __restrict__ src) {
    int i = blockIdx.x * 256 + threadIdx.x;      // < 147456
    float4 v = reinterpret_cast<const float4*>(src)[i];
    __nv_bfloat162* d2 = reinterpret_cast<__nv_bfloat162*>(g_wq_bf);
    d2[2 * i]     = __floats2bfloat162_rn(v.x, v.y);
    d2[2 * i + 1] = __floats2bfloat162_rn(v.z, v.w);
}

// ---------------------------------------------------------------------------
// context projections + layernorm -> g_ln
// ---------------------------------------------------------------------------
__global__ void cab_ctx_a_kernel(const float* __restrict__ ptk, const float* __restrict__ obj,
                                 const float* __restrict__ wpar, const float* __restrict__ bpar,
                                 const float* __restrict__ wobj, const float* __restrict__ bobj,
                                 const float* __restrict__ cnw, const float* __restrict__ cnb) {
    __shared__ float sprm[P_], sobj[O_];
    __shared__ float rbuf[8][4];
    __shared__ float stats[4];
    const int tid = threadIdx.x, lane = tid & 31, wid = tid >> 5;
    const int b = blockIdx.x;

    for (int i = tid; i < P_; i += 256) sprm[i] = ptk[b * P_ + i];
    if (tid < O_) sobj[tid] = obj[b * O_ + tid];
    __syncthreads();

    float pv[3], ov[3];
    float s_p = 0.f, q_p = 0.f, s_o = 0.f, q_o = 0.f;
    #pragma unroll
    for (int u = 0; u < 3; ++u) {
        const int c = tid + 256 * u;
        float ap = bpar[c];
        #pragma unroll 8
        for (int j = 0; j < P_; ++j) ap += sprm[j] * wpar[j * C_ + c];
        float ao = bobj[c];
        #pragma unroll 8
        for (int j = 0; j < O_; ++j) ao += sobj[j] * wobj[j * C_ + c];
        pv[u] = ap; ov[u] = ao;
        s_p += ap; q_p += ap * ap; s_o += ao; q_o += ao * ao;
    }
    #pragma unroll
    for (int o = 16; o; o >>= 1) {
        s_p += __shfl_xor_sync(~0u, s_p, o);
        q_p += __shfl_xor_sync(~0u, q_p, o);
        s_o += __shfl_xor_sync(~0u, s_o, o);
        q_o += __shfl_xor_sync(~0u, q_o, o);
    }
    if (lane == 0) { rbuf[wid][0] = s_p; rbuf[wid][1] = q_p; rbuf[wid][2] = s_o; rbuf[wid][3] = q_o; }
    __syncthreads();
    if (tid == 0) {
        float a = 0.f, bq = 0.f, cc = 0.f, d = 0.f;
        for (int w = 0; w < 8; ++w) { a += rbuf[w][0]; bq += rbuf[w][1]; cc += rbuf[w][2]; d += rbuf[w][3]; }
        const float mp = a / C_,  vp2 = bq / C_ - mp * mp;
        const float mo = cc / C_, vo  = d / C_ - mo * mo;
        stats[0] = mp; stats[1] = rsqrtf(vp2 + 1e-5f);
        stats[2] = mo; stats[3] = rsqrtf(vo + 1e-5f);
    }
    __syncthreads();
    const float mp = stats[0], rp = stats[1], mo = stats[2], ro = stats[3];
    #pragma unroll
    for (int u = 0; u < 3; ++u) {
        const int c = tid + 256 * u;
        g_ln[(b * 2 + 0) * C_ + c] = (pv[u] - mp) * rp * cnw[c] + cnb[c];
        g_ln[(b * 2 + 1) * C_ + c] = (ov[u] - mo) * ro * cnw[c] + cnb[c];
    }
}

// ---------------------------------------------------------------------------
// kv = LN(ctx) @ w_kv  -- split-K, coalesced.  grid (12, B_), block 256
// ---------------------------------------------------------------------------
__global__ void __launch_bounds__(256)
cab_ctx_b_kernel(const float* __restrict__ wkv) {
    __shared__ float ln0[C_], ln1[C_];
    __shared__ float red[2][128];
    const int tid = threadIdx.x;
    const int b = blockIdx.y;
    const int ks = tid >> 7;            // 0/1 : K half
    const int cc = tid & 127;
    const int col = blockIdx.x * 128 + cc;   // 0..1535

    for (int i = tid; i < C_; i += 256) {
        ln0[i] = g_ln[(b * 2 + 0) * C_ + i];
        ln1[i] = g_ln[(b * 2 + 1) * C_ + i];
    }
    __syncthreads();

    float a0 = 0.f, a1 = 0.f;
    const int k0 = ks * 384;
    #pragma unroll 8
    for (int k = 0; k < 384; ++k) {
        const float w = wkv[(size_t)(k0 + k) * (2 * C_) + col];
        a0 += ln0[k0 + k] * w;
        a1 += ln1[k0 + k] * w;
    }
    if (ks == 1) { red[0][cc] = a0; red[1][cc] = a1; }
    __syncthreads();
    if (ks == 0) {
        a0 += red[0][cc];
        a1 += red[1][cc];
        if (col < C_) {
            g_k[(b * 2 + 0) * C_ + col] = a0;
            g_k[(b * 2 + 1) * C_ + col] = a1;
        } else {
            g_v[(b * 2 + 0) * C_ + col - C_] = a0;
            g_v[(b * 2 + 1) * C_ + col - C_] = a1;
        }
    }
}

// ---------------------------------------------------------------------------
// vp[b][c*12+h][:] = v_c[h slice] @ w_out[h slice, :]   (fp32, store bf16)
// grid (6, 12), block 128
// ---------------------------------------------------------------------------
__global__ void __launch_bounds__(128)
cab_vproj_kernel(const float* __restrict__ wout) {
    __shared__ float sv[32][64];          // [b*2+c][d]
    const int tid = threadIdx.x;
    const int h = blockIdx.y;
    const int col = blockIdx.x * 128 + tid;

    for (int l = tid; l < 32 * 64; l += 128) {
        const int i = l >> 6, d = l & 63;
        sv[i][d] = g_v[i * C_ + h * D_ + d];
    }
    __syncthreads();

    float acc[32];
    #pragma unroll
    for (int i = 0; i < 32; ++i) acc[i] = 0.f;
    #pragma unroll 4
    for (int d = 0; d < 64; ++d) {
        const float w = wout[(size_t)(h * D_ + d) * C_ + col];
        #pragma unroll
        for (int i = 0; i < 32; ++i) acc[i] += sv[i][d] * w;
    }
    #pragma unroll
    for (int i = 0; i < 32; ++i) {
        const int bb = i >> 1, c = i & 1;
        g_vp[((size_t)bb * 32 + c * 12 + h) * C_ + col] = __float2bfloat16(acc[i]);
    }
}

// ---------------------------------------------------------------------------
// main fused kernel: LN -> q GEMM (cp.async pipelined) -> softmax weights ->
// combine (watt @ vp) + bias + residual
// grid (32, 16), block 256, dyn smem SMEM_MAIN
// ---------------------------------------------------------------------------
__global__ void __launch_bounds__(256)
cab_main_kernel(const float* __restrict__ x,
                const float* __restrict__ lw, const float* __restrict__ lb,
                const float* __restrict__ bout, float* __restrict__ out) {
    extern __shared__ unsigned char sm[];
    __nv_bfloat16* xn   = reinterpret_cast<__nv_bfloat16*>(sm);
    __nv_bfloat16* bt   = reinterpret_cast<__nv_bfloat16*>(sm + SMEM_XN);
    float*         kk   = reinterpret_cast<float*>(sm + SMEM_XN + 2 * SMEM_BTB);
    __nv_bfloat16* watt = reinterpret_cast<__nv_bfloat16*>(sm + SMEM_XN + 2 * SMEM_BTB + SMEM_KK);

    const int tid = threadIdx.x, lane = tid & 31, wid = tid >> 5;
    const int b = blockIdx.y, row0 = blockIdx.x * TM;
    const int wm = wid & 3, wn = wid >> 2;

    const uint32_t xnb = (uint32_t)__cvta_generic_to_shared(xn);
    const uint32_t btb = (uint32_t)__cvta_generic_to_shared(bt);
    const uint32_t wtb = (uint32_t)__cvta_generic_to_shared(watt);

    // zero watt (pad cols must be finite) + load k
    for (int i = tid; i < TM * WTS / 2; i += 256)
        reinterpret_cast<uint32_t*>(watt)[i] = 0u;
    for (int i = tid; i < 2 * C_; i += 256) kk[i] = g_k[b * 2 * C_ + i];

    // ---- stage 0: layernorm 128 rows -> bf16 A tile ----
    float2 wv[12], bv[12];
    #pragma unroll
    for (int i = 0; i < 12; ++i) {
        wv[i] = *reinterpret_cast<const float2*>(lw + 2 * lane + 64 * i);
        bv[i] = *reinterpret_cast<const float2*>(lb + 2 * lane + 64 * i);
    }
    for (int r = 0; r < 16; ++r) {
        const int row = wid * 16 + r;
        const float2* xr = reinterpret_cast<const float2*>(
            x + ((size_t)b * NIMG + row0 + row) * C_);
        float2 xv[12];
        float s = 0.f, s2 = 0.f;
        #pragma unroll
        for (int i = 0; i < 12; ++i) {
            const float2 t = xr[lane + 32 * i];
            xv[i] = t;
            s  += t.x + t.y;
            s2 += t.x * t.x + t.y * t.y;
        }
        #pragma unroll
        for (int o = 16; o; o >>= 1) {
            s  += __shfl_xor_sync(~0u, s,  o);
            s2 += __shfl_xor_sync(~0u, s2, o);
        }
        const float mean = s * (1.f / C_);
        const float var  = s2 * (1.f / C_) - mean * mean;
        const float rstd = rsqrtf(var + 1e-5f);
        __nv_bfloat16* xrow = xn + row * XS;
        #pragma unroll
        for (int i = 0; i < 12; ++i) {
            const float a0 = (xv[i].x - mean) * rstd * wv[i].x + bv[i].x;
            const float a1 = (xv[i].y - mean) * rstd * wv[i].y + bv[i].y;
            *reinterpret_cast<__nv_bfloat162*>(xrow + 2 * lane + 64 * i) =
                __floats2bfloat162_rn(a0, a1);
        }
    }
    __syncthreads();

    // ---- stage 1: q GEMM per 128-col chunk + attention epilogue ----
    const int c0 = tid & 15;            // uint4 index within row
    const int r0i = tid >> 4;           // rows 0..15 (j adds 16)
    for (int ncx = 0; ncx < 6; ++ncx) {
        float acc[2][8][4];
        #pragma unroll
        for (int mi = 0; mi < 2; ++mi)
            #pragma unroll
            for (int ni = 0; ni < 8; ++ni)
                #pragma unroll
                for (int r = 0; r < 4; ++r) acc[mi][ni][r] = 0.f;

        // prologue: tile 0 -> buf0
        #pragma unroll
        for (int j = 0; j < 2; ++j) {
            const int row = r0i + j * 16;
            cp16(btb + (row * BTS + c0 * 8) * 2,
                 g_wq_bf + (size_t)row * C_ + ncx * 128 + c0 * 8);
        }
        cp_commit();

        for (int kt = 0; kt < 24; ++kt) {
            cp_wait0();
            __syncthreads();
            if (kt + 1 < 24) {
                const uint32_t bnext = btb + ((kt + 1) & 1) * SMEM_BTB;
                #pragma unroll
                for (int j = 0; j < 2; ++j) {
                    const int row = r0i + j * 16;
                    cp16(bnext + (row * BTS + c0 * 8) * 2,
                         g_wq_bf + (size_t)((kt + 1) * BK + row) * C_ + ncx * 128 + c0 * 8);
                }
                cp_commit();
            }
            const uint32_t bcur = btb + (kt & 1) * SMEM_BTB;
            #pragma unroll
            for (int ks = 0; ks < 2; ++ks) {
                const int kb = kt * BK + ks * 16;
                uint32_t a0[4], a1[4];
                ldsm4(a0, xnb + (((wm * 32 +      (lane & 15)) * XS + kb + (lane >> 4) * 8) << 1));
                ldsm4(a1, xnb + (((wm * 32 + 16 + (lane & 15)) * XS + kb + (lane >> 4) * 8) << 1));
                #pragma unroll
                for (int nt = 0; nt < 4; ++nt) {
                    uint32_t bb4[4];
                    ldsm4t(bb4, bcur + (((ks * 16 + (lane & 15)) * BTS +
                                         wn * 64 + nt * 16 + (lane >> 4) * 8) << 1));
                    mma16816(acc[0][2 * nt],     a0, bb4);
                    mma16816(acc[0][2 * nt + 1], a0, bb4 + 2);
                    mma16816(acc[1][2 * nt],     a1, bb4);
                    mma16816(acc[1][2 * nt + 1], a1, bb4 + 2);
                }
            }
        }

        // attention epilogue: softmax-over-2 weights into watt
        const int head = ncx * 2 + wn;
        const float* k0p = kk + head * D_;
        const float* k1p = kk + C_ + head * D_;
        #pragma unroll
        for (int mi = 0; mi < 2; ++mi) {
            #pragma unroll
            for (int rh = 0; rh < 2; ++rh) {
                float p0 = 0.f, p1 = 0.f;
                #pragma unroll
                for (int ni = 0; ni < 8; ++ni) {
                    #pragma unroll
                    for (int rl = 0; rl < 2; ++rl) {
                        const int cl = ni * 8 + (lane & 3) * 2 + rl;
                        const float qv = acc[mi][ni][rh * 2 + rl];
                        p0 += qv * k0p[cl];
                        p1 += qv * k1p[cl];
                    }
                }
                p0 += __shfl_xor_sync(~0u, p0, 1); p0 += __shfl_xor_sync(~0u, p0, 2);
                p1 += __shfl_xor_sync(~0u, p1, 1); p1 += __shfl_xor_sync(~0u, p1, 2);
                if ((lane & 3) == 0) {
                    const float s0 = p0 * 0.125f, s1 = p1 * 0.125f;
                    const float mx = fmaxf(s0, s1);
                    const float e0 = __expf(s0 - mx), e1 = __expf(s1 - mx);
                    const float w0 = e0 / (e0 + e1);
                    const int rl = wm * 32 + mi * 16 + (lane >> 2) + rh * 8;
                    watt[rl * WTS + head]      = __float2bfloat16(w0);
                    watt[rl * WTS + 12 + head] = __float2bfloat16(1.f - w0);
                }
            }
        }
    }

    // ---- stage 2: out = watt @ vp + bias + residual ----
    for (int ncx = 0; ncx < 6; ++ncx) {
        __nv_bfloat16* bcurp = bt + (ncx & 1) * (SMEM_BTB / 2);
        const uint32_t bcur = btb + (ncx & 1) * SMEM_BTB;
        #pragma unroll
        for (int j = 0; j < 2; ++j) {
            const int row = r0i + j * 16;
            *reinterpret_cast<uint4*>(bcurp + row * BTS + c0 * 8) =
                *reinterpret_cast<const uint4*>(
                    g_vp + ((size_t)b * 32 + row) * C_ + ncx * 128 + c0 * 8);
        }
        __syncthreads();

        float acc[2][8][4];
        #pragma unroll
        for (int mi = 0; mi < 2; ++mi)
            #pragma unroll
            for (int ni = 0; ni < 8; ++ni)
                #pragma unroll
                for (int r = 0; r < 4; ++r) acc[mi][ni][r] = 0.f;

        #pragma unroll
        for (int ks = 0; ks < 2; ++ks) {
            uint32_t a0[4], a1[4];
            ldsm4(a0, wtb + (((wm * 32 +      (lane & 15)) * WTS + ks * 16 + (lane >> 4) * 8) << 1));
            ldsm4(a1, wtb + (((wm * 32 + 16 + (lane & 15)) * WTS + ks * 16 + (lane >> 4) * 8) << 1));
            #pragma unroll
            for (int nt = 0; nt < 4; ++nt) {
                uint32_t bb4[4];
                ldsm4t(bb4, bcur + (((ks * 16 + (lane & 15)) * BTS +
                                     wn * 64 + nt * 16 + (lane >> 4) * 8) << 1));
                mma16816(acc[0][2 * nt],     a0, bb4);
                mma16816(acc[0][2 * nt + 1], a0, bb4 + 2);
                mma16816(acc[1][2 * nt],     a1, bb4);
                mma16816(acc[1][2 * nt + 1], a1, bb4 + 2);
            }
        }

        #pragma unroll
        for (int mi = 0; mi < 2; ++mi) {
            #pragma unroll
            for (int rh = 0; rh < 2; ++rh) {
                const int rg = row0 + wm * 32 + mi * 16 + (lane >> 2) + rh * 8;
                const float* xr = x + ((size_t)b * NIMG + rg) * C_;
                float* orow = out + ((size_t)b * NIMG + rg) * C_;
                #pragma unroll
                for (int ni = 0; ni < 8; ++ni) {
                    const int col = ncx * 128 + wn * 64 + ni * 8 + (lane & 3) * 2;
                    const float2 xv = *reinterpret_cast<const float2*>(xr + col);
                    const float2 bo = *reinterpret_cast<const float2*>(bout + col);
                    float2 rr;
                    rr.x = acc[mi][ni][rh * 2 + 0] + bo.x + xv.x;
                    rr.y = acc[mi][ni][rh * 2 + 1] + bo.y + xv.y;
                    *reinterpret_cast<float2*>(orow + col) = rr;
                }
            }
        }
    }
}

// ---------------------------------------------------------------------------
// launch
// ---------------------------------------------------------------------------
extern "C" void kernel_launch(void* const* d_in, const int* in_sizes, int n_in,
                              void* d_out, int out_size) {
    const float* x    = (const float*)d_in[0];
    const float* ptk  = (const float*)d_in[1];
    const float* obj  = (const float*)d_in[2];
    const float* inw  = (const float*)d_in[3];
    const float* inb  = (const float*)d_in[4];
    const float* cnw  = (const float*)d_in[5];
    const float* cnb  = (const float*)d_in[6];
    const float* wq   = (const float*)d_in[7];
    const float* wpar = (const float*)d_in[8];
    const float* bpar = (const float*)d_in[9];
    const float* wobj = (const float*)d_in[10];
    const float* bobj = (const float*)d_in[11];
    const float* wkv  = (const float*)d_in[12];
    const float* wout = (const float*)d_in[13];
    const float* bout = (const float*)d_in[14];
    float* out = (float*)d_out;

    cudaFuncSetAttribute(cab_main_kernel,
                         cudaFuncAttributeMaxDynamicSharedMemorySize, SMEM_MAIN);

    cab_cvt_kernel<<<576, 256>>>(wq);
    cab_ctx_a_kernel<<<B_, 256>>>(ptk, obj, wpar, bpar, wobj, bobj, cnw, cnb);
    cab_ctx_b_kernel<<<dim3(12, B_), 256>>>(wkv);
    cab_vproj_kernel<<<dim3(6, H_), 128>>>(wout);
    cab_main_kernel<<<dim3(NIMG / TM, B_), 256, SMEM_MAIN>>>(x, inw, inb, bout, out);
}